// round 4
// baseline (speedup 1.0000x reference)
#include <cuda_runtime.h>
#include <cuda_fp16.h>
#include <cstdint>
#include <cstddef>

// ---------------------------------------------------------------------------
// Out[b] = [W_e | W_h](128x256) @ [e_vw[b]; h_w[b]](256x512) + (b_e + b_h)
// B=1024, M=128, K=256, N=512.
// sm_103-portable path: fp16 mma.sync.m16n8k16 (fallback HMMA), ldmatrix,
// double-buffered smem with LDG prefetch. No tcgen05 / TMA / cluster features
// (ptxas target is plain sm_103, 'a'-features rejected).
// ---------------------------------------------------------------------------

#define A_PITCH_H   40    // halves per A row  (80 B)  -> conflict-free ldmatrix
#define B_PITCH_H   136   // halves per B row  (272 B) -> conflict-free ldmatrix
#define A_BUF_BYTES (128 * A_PITCH_H * 2)   // 10240
#define B_BUF_BYTES (32  * B_PITCH_H * 2)   // 8704
#define EPI_PITCH   132                     // floats, 528 B rows (16B aligned)
#define SMEM_TOTAL  (128 * EPI_PITCH * 4)   // 67584 >= 2*(A+B) buffers (37888)

static __device__ __forceinline__ uint32_t smem_u32(const void* p) {
    uint32_t a;
    asm("{ .reg .u64 t; cvta.to.shared.u64 t, %1; cvt.u32.u64 %0, t; }"
        : "=r"(a) : "l"(p));
    return a;
}

static __device__ __forceinline__ void ldmx4(uint32_t* r, uint32_t addr) {
    asm volatile("ldmatrix.sync.aligned.m8n8.x4.shared.b16 {%0,%1,%2,%3}, [%4];"
                 : "=r"(r[0]), "=r"(r[1]), "=r"(r[2]), "=r"(r[3]) : "r"(addr));
}
static __device__ __forceinline__ void ldmx4t(uint32_t* r, uint32_t addr) {
    asm volatile("ldmatrix.sync.aligned.m8n8.x4.trans.shared.b16 {%0,%1,%2,%3}, [%4];"
                 : "=r"(r[0]), "=r"(r[1]), "=r"(r[2]), "=r"(r[3]) : "r"(addr));
}
static __device__ __forceinline__ void mma16816(float* d, const uint32_t* a,
                                                uint32_t b0, uint32_t b1) {
    asm volatile(
        "mma.sync.aligned.m16n8k16.row.col.f32.f16.f16.f32 "
        "{%0,%1,%2,%3}, {%4,%5,%6,%7}, {%8,%9}, {%0,%1,%2,%3};"
        : "+f"(d[0]), "+f"(d[1]), "+f"(d[2]), "+f"(d[3])
        : "r"(a[0]), "r"(a[1]), "r"(a[2]), "r"(a[3]), "r"(b0), "r"(b1));
}

static __device__ __forceinline__ uint32_t packh2(float x, float y) {
    __half2 h = __floats2half2_rn(x, y);
    return *reinterpret_cast<uint32_t*>(&h);
}

__global__ __launch_bounds__(256, 1)
void msg_kernel(const float* __restrict__ h_w, const float* __restrict__ e_vw,
                const float* __restrict__ W_e, const float* __restrict__ b_e,
                const float* __restrict__ W_h, const float* __restrict__ b_h,
                float* __restrict__ out) {
    extern __shared__ char smem[];
    __shared__ float sbias[128];

    const int tid  = threadIdx.x;
    const int lane = tid & 31;
    const int wid  = tid >> 5;
    const int b    = blockIdx.y;
    const int n0   = blockIdx.x << 7;          // 0,128,256,384

    if (tid < 128) sbias[tid] = b_e[tid] + b_h[tid];

    __half* Abuf[2] = { reinterpret_cast<__half*>(smem),
                        reinterpret_cast<__half*>(smem + A_BUF_BYTES) };
    __half* Bbuf[2] = { reinterpret_cast<__half*>(smem + 2 * A_BUF_BYTES),
                        reinterpret_cast<__half*>(smem + 2 * A_BUF_BYTES + B_BUF_BYTES) };

    const float* Xe = e_vw + (size_t)b * 65536 + n0;   // [128 K][512 N] slab
    const float* Xh = h_w  + (size_t)b * 65536 + n0;

    float4 rA[4], rB[4];

    auto ldg_chunk = [&](int i) {
        const int k0 = i << 5;
        const float* W = (k0 < 128) ? (W_e + k0) : (W_h + (k0 - 128));
        const float* X = (k0 < 128) ? (Xe + (size_t)k0 * 512)
                                    : (Xh + (size_t)(k0 - 128) * 512);
        #pragma unroll
        for (int s = 0; s < 4; s++) {
            const int idx = tid + (s << 8);
            // A: [128 m][32 k] fp32; warp = 4 W-rows, coalesced 128B segments
            const int m  = idx >> 3, kk = (idx & 7) << 2;
            rA[s] = *reinterpret_cast<const float4*>(W + m * 128 + kk);
            // B: [32 k][128 n] fp32; warp = one full 512B row, coalesced
            const int k  = idx >> 5, n4 = (idx & 31) << 2;
            rB[s] = *reinterpret_cast<const float4*>(X + (size_t)k * 512 + n4);
        }
    };

    auto sts_chunk = [&](int buf) {
        __half* A = Abuf[buf];
        __half* B = Bbuf[buf];
        #pragma unroll
        for (int s = 0; s < 4; s++) {
            const int idx = tid + (s << 8);
            const int m  = idx >> 3, kk = (idx & 7) << 2;
            uint32_t* pa = reinterpret_cast<uint32_t*>(A + m * A_PITCH_H + kk);
            pa[0] = packh2(rA[s].x, rA[s].y);
            pa[1] = packh2(rA[s].z, rA[s].w);
            const int k  = idx >> 5, n4 = (idx & 31) << 2;
            uint32_t* pb = reinterpret_cast<uint32_t*>(B + k * B_PITCH_H + n4);
            pb[0] = packh2(rB[s].x, rB[s].y);
            pb[1] = packh2(rB[s].z, rB[s].w);
        }
    };

    const int wm = (wid >> 2) << 6;     // 0 or 64
    const int wn = (wid & 3) << 5;      // 0,32,64,96
    float acc[4][4][4];
    #pragma unroll
    for (int i = 0; i < 4; i++)
        #pragma unroll
        for (int j = 0; j < 4; j++)
            #pragma unroll
            for (int r = 0; r < 4; r++) acc[i][j][r] = 0.f;

    auto compute = [&](int buf) {
        __half* A = Abuf[buf];
        __half* B = Bbuf[buf];
        const int j8  = lane & 7;
        const int sel = lane >> 3;
        #pragma unroll
        for (int ks = 0; ks < 2; ks++) {
            const int kk = ks << 4;
            uint32_t afr[4][4];
            #pragma unroll
            for (int i = 0; i < 4; i++) {
                // x4 tiles: [m0 k0][m8 k0][m0 k8][m8 k8]
                const int row = wm + (i << 4) + ((sel & 1) << 3) + j8;
                const int kh  = kk + ((sel >> 1) << 3);
                ldmx4(afr[i], smem_u32(A + row * A_PITCH_H + kh));
            }
            uint32_t bfr[2][4];
            #pragma unroll
            for (int g = 0; g < 2; g++) {
                // trans tiles: [k0 n0][k8 n0][k0 n8][k8 n8]
                const int kr = kk + ((sel & 1) << 3) + j8;
                const int nc = wn + (g << 4) + ((sel >> 1) << 3);
                ldmx4t(bfr[g], smem_u32(B + kr * B_PITCH_H + nc));
            }
            #pragma unroll
            for (int i = 0; i < 4; i++)
                #pragma unroll
                for (int j = 0; j < 4; j++)
                    mma16816(acc[i][j], afr[i], bfr[j >> 1][(j & 1) << 1],
                             bfr[j >> 1][((j & 1) << 1) + 1]);
        }
    };

    // -------- pipeline: prologue --------
    ldg_chunk(0);
    sts_chunk(0);
    __syncthreads();

    // -------- mainloop: 8 K-chunks of 32 --------
    for (int i = 0; i < 8; i++) {
        if (i + 1 < 8) ldg_chunk(i + 1);    // prefetch under the MMAs
        compute(i & 1);
        __syncthreads();
        if (i + 1 < 8) {
            sts_chunk((i + 1) & 1);
            __syncthreads();
        }
    }
    __syncthreads();

    // -------- epilogue: regs -> smem (pitch 132) -> coalesced STG --------
    float* E = reinterpret_cast<float*>(smem);
    {
        const int r0 = lane >> 2;
        const int c0 = (lane & 3) << 1;
        #pragma unroll
        for (int i = 0; i < 4; i++)
            #pragma unroll
            for (int j = 0; j < 4; j++) {
                const int r = wm + (i << 4) + r0;
                const int c = wn + (j << 3) + c0;
                E[r * EPI_PITCH + c]           = acc[i][j][0];
                E[r * EPI_PITCH + c + 1]       = acc[i][j][1];
                E[(r + 8) * EPI_PITCH + c]     = acc[i][j][2];
                E[(r + 8) * EPI_PITCH + c + 1] = acc[i][j][3];
            }
    }
    __syncthreads();

    float* outp = out + (size_t)b * 65536 + n0;
    #pragma unroll
    for (int s = 0; s < 16; s++) {
        const int idx = tid + (s << 8);        // 4096 float4 slots (128 x 32)
        const int m = idx >> 5, c4 = (idx & 31) << 2;
        const float bias = sbias[m];
        float4 v = *reinterpret_cast<const float4*>(E + m * EPI_PITCH + c4);
        v.x += bias; v.y += bias; v.z += bias; v.w += bias;
        *reinterpret_cast<float4*>(outp + (size_t)m * 512 + c4) = v;
    }
}

extern "C" void kernel_launch(void* const* d_in, const int* in_sizes, int n_in,
                              void* d_out, int out_size) {
    // metadata order: h_v(unused), h_w, e_vw, W_e, b_e, W_h, b_h
    const float* h_w  = (const float*)d_in[1];
    const float* e_vw = (const float*)d_in[2];
    const float* W_e  = (const float*)d_in[3];
    const float* b_e  = (const float*)d_in[4];
    const float* W_h  = (const float*)d_in[5];
    const float* b_h  = (const float*)d_in[6];
    float* out = (float*)d_out;

    cudaFuncSetAttribute(msg_kernel, cudaFuncAttributeMaxDynamicSharedMemorySize,
                         SMEM_TOTAL);
    dim3 grid(4, 1024);
    msg_kernel<<<grid, 256, SMEM_TOTAL>>>(h_w, e_vw, W_e, b_e, W_h, b_h, out);
}

// round 5
// speedup vs baseline: 1.2185x; 1.2185x over previous
#include <cuda_runtime.h>
#include <cuda_fp16.h>
#include <cstdint>
#include <cstddef>

// ---------------------------------------------------------------------------
// Out[b] = [W_e | W_h](128x256) @ [e_vw[b]; h_w[b]](256x512) + (b_e + b_h)
// B=1024, M=128, K=256, N=512.
// fp16 mma.sync.m16n8k16, ldmatrix, double-buffered smem, pack-early prefetch,
// single barrier per K-chunk, direct-STG epilogue, 2 CTAs/SM.
// ---------------------------------------------------------------------------

#define A_PITCH_H   40    // halves per A row  (80 B)  -> conflict-free ldmatrix
#define B_PITCH_H   136   // halves per B row  (272 B) -> conflict-free ldmatrix
#define A_BUF_BYTES (128 * A_PITCH_H * 2)   // 10240
#define B_BUF_BYTES (32  * B_PITCH_H * 2)   // 8704
#define SMEM_TOTAL  (2 * (A_BUF_BYTES + B_BUF_BYTES))   // 37888

static __device__ __forceinline__ uint32_t smem_u32(const void* p) {
    uint32_t a;
    asm("{ .reg .u64 t; cvta.to.shared.u64 t, %1; cvt.u32.u64 %0, t; }"
        : "=r"(a) : "l"(p));
    return a;
}

static __device__ __forceinline__ void ldmx4(uint32_t* r, uint32_t addr) {
    asm volatile("ldmatrix.sync.aligned.m8n8.x4.shared.b16 {%0,%1,%2,%3}, [%4];"
                 : "=r"(r[0]), "=r"(r[1]), "=r"(r[2]), "=r"(r[3]) : "r"(addr));
}
static __device__ __forceinline__ void ldmx4t(uint32_t* r, uint32_t addr) {
    asm volatile("ldmatrix.sync.aligned.m8n8.x4.trans.shared.b16 {%0,%1,%2,%3}, [%4];"
                 : "=r"(r[0]), "=r"(r[1]), "=r"(r[2]), "=r"(r[3]) : "r"(addr));
}
static __device__ __forceinline__ void mma16816(float* d, const uint32_t* a,
                                                uint32_t b0, uint32_t b1) {
    asm volatile(
        "mma.sync.aligned.m16n8k16.row.col.f32.f16.f16.f32 "
        "{%0,%1,%2,%3}, {%4,%5,%6,%7}, {%8,%9}, {%0,%1,%2,%3};"
        : "+f"(d[0]), "+f"(d[1]), "+f"(d[2]), "+f"(d[3])
        : "r"(a[0]), "r"(a[1]), "r"(a[2]), "r"(a[3]), "r"(b0), "r"(b1));
}

static __device__ __forceinline__ uint32_t packh2(float x, float y) {
    __half2 h = __floats2half2_rn(x, y);
    return *reinterpret_cast<uint32_t*>(&h);
}

__global__ __launch_bounds__(256, 2)
void msg_kernel(const float* __restrict__ h_w, const float* __restrict__ e_vw,
                const float* __restrict__ W_e, const float* __restrict__ b_e,
                const float* __restrict__ W_h, const float* __restrict__ b_h,
                float* __restrict__ out) {
    extern __shared__ char smem[];
    __shared__ float sbias[128];

    const int tid  = threadIdx.x;
    const int lane = tid & 31;
    const int wid  = tid >> 5;
    const int b    = blockIdx.y;
    const int n0   = blockIdx.x << 7;          // 0,128,256,384

    if (tid < 128) sbias[tid] = b_e[tid] + b_h[tid];

    __half* Abuf[2] = { reinterpret_cast<__half*>(smem),
                        reinterpret_cast<__half*>(smem + A_BUF_BYTES) };
    __half* Bbuf[2] = { reinterpret_cast<__half*>(smem + 2 * A_BUF_BYTES),
                        reinterpret_cast<__half*>(smem + 2 * A_BUF_BYTES + B_BUF_BYTES) };

    const float* Xe = e_vw + (size_t)b * 65536 + n0;   // [128 K][512 N] slab
    const float* Xh = h_w  + (size_t)b * 65536 + n0;

    // Pack-early prefetch registers: 8 u32 for A halves, 8 u32 for B halves.
    uint32_t pA[8], pB[8];

    // Per-thread source indices (constant across chunks)
    const int am = tid >> 3, akk = (tid & 7) << 2;       // A: 128 rows x 32 k / 2 passes
    const int bk = tid >> 6, bn4 = (tid & 63) << 1;      // B: 32 k x 128 n / ... (recomputed below)

    auto ldg_chunk = [&](int i) {
        const int k0 = i << 5;
        const float* W = (k0 < 128) ? (W_e + k0) : (W_h + (k0 - 128));
        const float* X = (k0 < 128) ? (Xe + (size_t)k0 * 512)
                                    : (Xh + (size_t)(k0 - 128) * 512);
        #pragma unroll
        for (int s = 0; s < 4; s++) {
            const int idx = tid + (s << 8);
            // A: [128 m][32 k] fp32; coalesced 128B segments per warp
            const int m  = idx >> 3, kk = (idx & 7) << 2;
            float4 va = *reinterpret_cast<const float4*>(W + m * 128 + kk);
            pA[2 * s]     = packh2(va.x, va.y);
            pA[2 * s + 1] = packh2(va.z, va.w);
            // B: [32 k][128 n] fp32; warp = one 512B row, coalesced
            const int k  = idx >> 5, n4 = (idx & 31) << 2;
            float4 vb = *reinterpret_cast<const float4*>(X + (size_t)k * 512 + n4);
            pB[2 * s]     = packh2(vb.x, vb.y);
            pB[2 * s + 1] = packh2(vb.z, vb.w);
        }
    };

    auto sts_chunk = [&](int buf) {
        __half* A = Abuf[buf];
        __half* B = Bbuf[buf];
        #pragma unroll
        for (int s = 0; s < 4; s++) {
            const int idx = tid + (s << 8);
            const int m  = idx >> 3, kk = (idx & 7) << 2;
            uint32_t* pa = reinterpret_cast<uint32_t*>(A + m * A_PITCH_H + kk);
            pa[0] = pA[2 * s];
            pa[1] = pA[2 * s + 1];
            const int k  = idx >> 5, n4 = (idx & 31) << 2;
            uint32_t* pb = reinterpret_cast<uint32_t*>(B + k * B_PITCH_H + n4);
            pb[0] = pB[2 * s];
            pb[1] = pB[2 * s + 1];
        }
    };

    const int wm = (wid >> 2) << 6;     // 0 or 64
    const int wn = (wid & 3) << 5;      // 0,32,64,96
    float acc[4][4][4];
    #pragma unroll
    for (int i = 0; i < 4; i++)
        #pragma unroll
        for (int j = 0; j < 4; j++)
            #pragma unroll
            for (int r = 0; r < 4; r++) acc[i][j][r] = 0.f;

    auto compute = [&](int buf) {
        __half* A = Abuf[buf];
        __half* B = Bbuf[buf];
        const int j8  = lane & 7;
        const int sel = lane >> 3;
        #pragma unroll
        for (int ks = 0; ks < 2; ks++) {
            const int kk = ks << 4;
            uint32_t afr[4][4];
            #pragma unroll
            for (int i = 0; i < 4; i++) {
                // x4 tiles: [m0 k0][m8 k0][m0 k8][m8 k8]
                const int row = wm + (i << 4) + ((sel & 1) << 3) + j8;
                const int kh  = kk + ((sel >> 1) << 3);
                ldmx4(afr[i], smem_u32(A + row * A_PITCH_H + kh));
            }
            uint32_t bfr[2][4];
            #pragma unroll
            for (int g = 0; g < 2; g++) {
                // trans tiles: [k0 n0][k8 n0][k0 n8][k8 n8]
                const int kr = kk + ((sel & 1) << 3) + j8;
                const int nc = wn + (g << 4) + ((sel >> 1) << 3);
                ldmx4t(bfr[g], smem_u32(B + kr * B_PITCH_H + nc));
            }
            #pragma unroll
            for (int i = 0; i < 4; i++)
                #pragma unroll
                for (int j = 0; j < 4; j++)
                    mma16816(acc[i][j], afr[i], bfr[j >> 1][(j & 1) << 1],
                             bfr[j >> 1][((j & 1) << 1) + 1]);
        }
    };

    // -------- prologue --------
    ldg_chunk(0);
    sts_chunk(0);
    __syncthreads();

    // -------- mainloop: 8 K-chunks, ONE barrier per chunk --------
    // WAR safety: the barrier after sts(i) proves all warps finished
    // compute(i-1) (program order), and compute(i) reads buf i&1 while
    // sts(i+1) writes buf (i+1)&1 — disjoint buffers. So no pre-STS barrier.
    for (int i = 0; i < 8; i++) {
        if (i + 1 < 8) ldg_chunk(i + 1);    // prefetch under the MMAs
        compute(i & 1);
        if (i + 1 < 8) {
            sts_chunk((i + 1) & 1);
            __syncthreads();
        }
    }

    // -------- epilogue: direct STG (32B-sector complete per lane quad) -----
    const int r0 = lane >> 2;
    const int c0 = (lane & 3) << 1;
    float* outp = out + (size_t)b * 65536 + n0;
    #pragma unroll
    for (int i = 0; i < 4; i++) {
        const int r  = wm + (i << 4) + r0;
        const float bias0 = sbias[r];
        const float bias1 = sbias[r + 8];
        #pragma unroll
        for (int j = 0; j < 4; j++) {
            const int c = wn + (j << 3) + c0;
            float2 v0 = make_float2(acc[i][j][0] + bias0, acc[i][j][1] + bias0);
            float2 v1 = make_float2(acc[i][j][2] + bias1, acc[i][j][3] + bias1);
            *reinterpret_cast<float2*>(outp + (size_t)r * 512 + c)       = v0;
            *reinterpret_cast<float2*>(outp + (size_t)(r + 8) * 512 + c) = v1;
        }
    }
}

extern "C" void kernel_launch(void* const* d_in, const int* in_sizes, int n_in,
                              void* d_out, int out_size) {
    // metadata order: h_v(unused), h_w, e_vw, W_e, b_e, W_h, b_h
    const float* h_w  = (const float*)d_in[1];
    const float* e_vw = (const float*)d_in[2];
    const float* W_e  = (const float*)d_in[3];
    const float* b_e  = (const float*)d_in[4];
    const float* W_h  = (const float*)d_in[5];
    const float* b_h  = (const float*)d_in[6];
    float* out = (float*)d_out;

    cudaFuncSetAttribute(msg_kernel, cudaFuncAttributeMaxDynamicSharedMemorySize,
                         SMEM_TOTAL);
    dim3 grid(4, 1024);
    msg_kernel<<<grid, 256, SMEM_TOTAL>>>(h_w, e_vw, W_e, b_e, W_h, b_h, out);
}

// round 6
// speedup vs baseline: 1.2425x; 1.0197x over previous
#include <cuda_runtime.h>
#include <cuda_fp16.h>
#include <cstdint>
#include <cstddef>

// ---------------------------------------------------------------------------
// Out[b] = [W_e | W_h](128x256) @ [e_vw[b]; h_w[b]](256x512) + (b_e + b_h)
// B=1024, M=128, K=256, N=512.
// fp16 mma.sync.m16n8k16. A(W): LDG(L2)->pack->STS fp16 double buffer (short
// latency). B(X): cp.async fp32 3-stage smem ring; fragments built straight
// from fp32 smem (LDS + pack), removing the DRAM long-scoreboard from the
// per-chunk critical path. 2 CTAs/SM.
// ---------------------------------------------------------------------------

#define A_PITCH_H    40                    // halves per A row (80 B)
#define A_BUF_BYTES  (128 * A_PITCH_H * 2) // 10240
#define B_PITCH_F    132                   // floats per B row -> conflict-free frag LDS
#define B_STAGE_BYTES (32 * B_PITCH_F * 4) // 16896
#define B_STAGES     3
#define SMEM_TOTAL   (2 * A_BUF_BYTES + B_STAGES * B_STAGE_BYTES)  // 71168

static __device__ __forceinline__ uint32_t smem_u32(const void* p) {
    uint32_t a;
    asm("{ .reg .u64 t; cvta.to.shared.u64 t, %1; cvt.u32.u64 %0, t; }"
        : "=r"(a) : "l"(p));
    return a;
}

static __device__ __forceinline__ void ldmx4(uint32_t* r, uint32_t addr) {
    asm volatile("ldmatrix.sync.aligned.m8n8.x4.shared.b16 {%0,%1,%2,%3}, [%4];"
                 : "=r"(r[0]), "=r"(r[1]), "=r"(r[2]), "=r"(r[3]) : "r"(addr));
}
static __device__ __forceinline__ void mma16816(float* d, const uint32_t* a,
                                                uint32_t b0, uint32_t b1) {
    asm volatile(
        "mma.sync.aligned.m16n8k16.row.col.f32.f16.f16.f32 "
        "{%0,%1,%2,%3}, {%4,%5,%6,%7}, {%8,%9}, {%0,%1,%2,%3};"
        : "+f"(d[0]), "+f"(d[1]), "+f"(d[2]), "+f"(d[3])
        : "r"(a[0]), "r"(a[1]), "r"(a[2]), "r"(a[3]), "r"(b0), "r"(b1));
}
static __device__ __forceinline__ uint32_t packh2(float x, float y) {
    __half2 h = __floats2half2_rn(x, y);
    return *reinterpret_cast<uint32_t*>(&h);
}
static __device__ __forceinline__ void cp16(uint32_t smem_addr, const float* g) {
    asm volatile("cp.async.cg.shared.global [%0], [%1], 16;"
                 :: "r"(smem_addr), "l"(g) : "memory");
}
static __device__ __forceinline__ void cp_commit() {
    asm volatile("cp.async.commit_group;" ::: "memory");
}
template <int N>
static __device__ __forceinline__ void cp_wait() {
    asm volatile("cp.async.wait_group %0;" :: "n"(N) : "memory");
}

__global__ __launch_bounds__(256, 2)
void msg_kernel(const float* __restrict__ h_w, const float* __restrict__ e_vw,
                const float* __restrict__ W_e, const float* __restrict__ b_e,
                const float* __restrict__ W_h, const float* __restrict__ b_h,
                float* __restrict__ out) {
    extern __shared__ char smem[];
    __shared__ float sbias[128];

    const int tid  = threadIdx.x;
    const int lane = tid & 31;
    const int wid  = tid >> 5;
    const int b    = blockIdx.y;
    const int n0   = blockIdx.x << 7;          // 0,128,256,384

    if (tid < 128) sbias[tid] = b_e[tid] + b_h[tid];

    __half* Abuf[2] = { reinterpret_cast<__half*>(smem),
                        reinterpret_cast<__half*>(smem + A_BUF_BYTES) };
    float* Bstage0 = reinterpret_cast<float*>(smem + 2 * A_BUF_BYTES);

    const float* Xe = e_vw + (size_t)b * 65536 + n0;   // [128 K][512 N] slab
    const float* Xh = h_w  + (size_t)b * 65536 + n0;

    uint32_t pA[8];                    // A pack-early staging (L2-resident W)

    auto ldg_A = [&](int i) {
        const int k0 = i << 5;
        const float* W = (k0 < 128) ? (W_e + k0) : (W_h + (k0 - 128));
        #pragma unroll
        for (int s = 0; s < 4; s++) {
            const int idx = tid + (s << 8);
            const int m = idx >> 3, kk = (idx & 7) << 2;
            float4 v = *reinterpret_cast<const float4*>(W + m * 128 + kk);
            pA[2 * s]     = packh2(v.x, v.y);
            pA[2 * s + 1] = packh2(v.z, v.w);
        }
    };
    auto sts_A = [&](int buf) {
        __half* A = Abuf[buf];
        #pragma unroll
        for (int s = 0; s < 4; s++) {
            const int idx = tid + (s << 8);
            const int m = idx >> 3, kk = (idx & 7) << 2;
            uint32_t* pa = reinterpret_cast<uint32_t*>(A + m * A_PITCH_H + kk);
            pa[0] = pA[2 * s];
            pa[1] = pA[2 * s + 1];
        }
    };
    auto cp_B = [&](int i) {                      // chunk i -> stage i % 3
        const int k0 = i << 5;
        const float* X = (k0 < 128) ? (Xe + (size_t)k0 * 512)
                                    : (Xh + (size_t)(k0 - 128) * 512);
        const uint32_t st = smem_u32(Bstage0) + (uint32_t)(i % B_STAGES) * B_STAGE_BYTES;
        #pragma unroll
        for (int s = 0; s < 4; s++) {
            const int idx = tid + (s << 8);
            const int k = idx >> 5, n4 = (idx & 31) << 2;   // 32 rows x 128 n
            cp16(st + (uint32_t)(k * B_PITCH_F + n4) * 4, X + (size_t)k * 512 + n4);
        }
    };

    const int wm = (wid >> 2) << 6;     // 0 or 64
    const int wn = (wid & 3) << 5;      // 0,32,64,96
    float acc[4][4][4];
    #pragma unroll
    for (int i = 0; i < 4; i++)
        #pragma unroll
        for (int j = 0; j < 4; j++)
            #pragma unroll
            for (int r = 0; r < 4; r++) acc[i][j][r] = 0.f;

    const int j8  = lane & 7;
    const int sel = lane >> 3;
    const int bn  = wn + (lane >> 2);        // B frag n column
    const int bk2 = (lane & 3) << 1;         // B frag k base within kstep

    auto compute = [&](int buf, int stage) {
        __half* A = Abuf[buf];
        const float* Bs = Bstage0 + stage * (B_STAGE_BYTES / 4);
        #pragma unroll
        for (int ks = 0; ks < 2; ks++) {
            const int kk = ks << 4;
            uint32_t afr[4][4];
            #pragma unroll
            for (int i = 0; i < 4; i++) {
                const int row = wm + (i << 4) + ((sel & 1) << 3) + j8;
                const int kh  = kk + ((sel >> 1) << 3);
                ldmx4(afr[i], smem_u32(A + row * A_PITCH_H + kh));
            }
            // B fragments straight from fp32 smem (canonical m16n8k16 layout):
            // b0=B[k][n], b1=B[k+1][n], b2=B[k+8][n], b3=B[k+9][n], k=kk+2*(lane&3)
            uint32_t bq[4][2];
            #pragma unroll
            for (int t = 0; t < 4; t++) {
                const float* p = Bs + (kk + bk2) * B_PITCH_F + bn + (t << 3);
                const float f0 = p[0];
                const float f1 = p[B_PITCH_F];
                const float f2 = p[8 * B_PITCH_F];
                const float f3 = p[9 * B_PITCH_F];
                bq[t][0] = packh2(f0, f1);
                bq[t][1] = packh2(f2, f3);
            }
            #pragma unroll
            for (int i = 0; i < 4; i++)
                #pragma unroll
                for (int t = 0; t < 4; t++)
                    mma16816(acc[i][t], afr[i], bq[t][0], bq[t][1]);
        }
    };

    // -------- prologue: A chunk 0 + B chunks 0,1 in flight --------
    ldg_A(0);
    sts_A(0);
    cp_B(0); cp_commit();
    cp_B(1); cp_commit();

    // -------- mainloop: 8 K-chunks --------
    // Group g == chunk g. At iter i (before this iter's commit) committed
    // groups are 0..i+1, chunk i ready when <=1 groups outstanding.
    for (int i = 0; i < 8; i++) {
        if (i < 7) cp_wait<1>(); else cp_wait<0>();
        __syncthreads();            // chunk-i B visible to all; compute(i-1)
                                    // done -> stage (i+2)%3 free; A buf ready
        if (i + 2 < 8) { cp_B(i + 2); cp_commit(); }
        if (i + 1 < 8) ldg_A(i + 1);            // L2-latency prefetch
        compute(i & 1, i % B_STAGES);
        if (i + 1 < 8) sts_A((i + 1) & 1);      // disjoint from buf i&1
    }

    // -------- epilogue: direct STG (32B-sector complete per lane quad) -----
    const int r0 = lane >> 2;
    const int c0 = (lane & 3) << 1;
    float* outp = out + (size_t)b * 65536 + n0;
    #pragma unroll
    for (int i = 0; i < 4; i++) {
        const int r  = wm + (i << 4) + r0;
        const float bias0 = sbias[r];
        const float bias1 = sbias[r + 8];
        #pragma unroll
        for (int j = 0; j < 4; j++) {
            const int c = wn + (j << 3) + c0;
            float2 v0 = make_float2(acc[i][j][0] + bias0, acc[i][j][1] + bias0);
            float2 v1 = make_float2(acc[i][j][2] + bias1, acc[i][j][3] + bias1);
            *reinterpret_cast<float2*>(outp + (size_t)r * 512 + c)       = v0;
            *reinterpret_cast<float2*>(outp + (size_t)(r + 8) * 512 + c) = v1;
        }
    }
}

extern "C" void kernel_launch(void* const* d_in, const int* in_sizes, int n_in,
                              void* d_out, int out_size) {
    // metadata order: h_v(unused), h_w, e_vw, W_e, b_e, W_h, b_h
    const float* h_w  = (const float*)d_in[1];
    const float* e_vw = (const float*)d_in[2];
    const float* W_e  = (const float*)d_in[3];
    const float* b_e  = (const float*)d_in[4];
    const float* W_h  = (const float*)d_in[5];
    const float* b_h  = (const float*)d_in[6];
    float* out = (float*)d_out;

    cudaFuncSetAttribute(msg_kernel, cudaFuncAttributeMaxDynamicSharedMemorySize,
                         SMEM_TOTAL);
    dim3 grid(4, 1024);
    msg_kernel<<<grid, 256, SMEM_TOTAL>>>(h_w, e_vw, W_e, b_e, W_h, b_h, out);
}

// round 8
// speedup vs baseline: 1.4328x; 1.1532x over previous
#include <cuda_runtime.h>
#include <cuda_fp16.h>
#include <cstdint>
#include <cstddef>

// ---------------------------------------------------------------------------
// Out[b] = [W_e | W_h](128x256) @ [e_vw[b]; h_w[b]](256x512) + (b_e + b_h)
// B=1024, M=128, K=256, N=512.
// Prep kernel: W -> fp16 global + fused bias (runs once per launch, ~3us).
// Main kernel: CTA tile 128x64, 8 warps x (32x32) tiles, 3 CTAs/SM.
// A: cp.async fp16 (prepacked) -> ldmatrix. B: cp.async fp32 -> LDS+pack.
// Unified 3-stage ring, one barrier per K-chunk.
// ---------------------------------------------------------------------------

#define A_PITCH_H     40                      // halves per A row (80 B)
#define A_STAGE_BYTES (128 * A_PITCH_H * 2)   // 10240
#define B_PITCH_F     68                      // floats per B row
#define B_STAGE_BYTES (32 * B_PITCH_F * 4)    // 8704
#define STAGES        3
#define SMEM_TOTAL    (STAGES * (A_STAGE_BYTES + B_STAGE_BYTES))  // 56832

__device__ __half g_W[128 * 256];     // [m][k] fp16, k-contiguous
__device__ float  g_bias[128];

__global__ __launch_bounds__(256)
void prep_kernel(const float* __restrict__ W_e, const float* __restrict__ W_h,
                 const float* __restrict__ b_e, const float* __restrict__ b_h) {
    const int idx = blockIdx.x * 256 + threadIdx.x;     // 0..32767
    const int m = idx >> 8, k = idx & 255;
    const float v = (k < 128) ? W_e[m * 128 + k] : W_h[m * 128 + (k - 128)];
    g_W[idx] = __float2half(v);
    if (idx < 128) g_bias[idx] = b_e[idx] + b_h[idx];
}

static __device__ __forceinline__ uint32_t smem_u32(const void* p) {
    uint32_t a;
    asm("{ .reg .u64 t; cvta.to.shared.u64 t, %1; cvt.u32.u64 %0, t; }"
        : "=r"(a) : "l"(p));
    return a;
}
static __device__ __forceinline__ void ldmx4(uint32_t* r, uint32_t addr) {
    asm volatile("ldmatrix.sync.aligned.m8n8.x4.shared.b16 {%0,%1,%2,%3}, [%4];"
                 : "=r"(r[0]), "=r"(r[1]), "=r"(r[2]), "=r"(r[3]) : "r"(addr));
}
static __device__ __forceinline__ void mma16816(float* d, const uint32_t* a,
                                                uint32_t b0, uint32_t b1) {
    asm volatile(
        "mma.sync.aligned.m16n8k16.row.col.f32.f16.f16.f32 "
        "{%0,%1,%2,%3}, {%4,%5,%6,%7}, {%8,%9}, {%0,%1,%2,%3};"
        : "+f"(d[0]), "+f"(d[1]), "+f"(d[2]), "+f"(d[3])
        : "r"(a[0]), "r"(a[1]), "r"(a[2]), "r"(a[3]), "r"(b0), "r"(b1));
}
static __device__ __forceinline__ uint32_t packh2(float x, float y) {
    __half2 h = __floats2half2_rn(x, y);
    return *reinterpret_cast<uint32_t*>(&h);
}
static __device__ __forceinline__ void cp16(uint32_t smem_addr, const void* g) {
    asm volatile("cp.async.cg.shared.global [%0], [%1], 16;"
                 :: "r"(smem_addr), "l"(g) : "memory");
}
static __device__ __forceinline__ void cp_commit() {
    asm volatile("cp.async.commit_group;" ::: "memory");
}
template <int N>
static __device__ __forceinline__ void cp_wait() {
    asm volatile("cp.async.wait_group %0;" :: "n"(N) : "memory");
}

__global__ __launch_bounds__(256, 3)
void msg_kernel(const float* __restrict__ h_w, const float* __restrict__ e_vw,
                float* __restrict__ out) {
    extern __shared__ char smem[];
    __shared__ float sbias[128];

    const int tid  = threadIdx.x;
    const int lane = tid & 31;
    const int wid  = tid >> 5;
    const int b    = blockIdx.y;
    const int n0   = blockIdx.x << 6;          // 0..448 step 64

    if (tid < 128) sbias[tid] = g_bias[tid];

    // ring layout: [A0 A1 A2 | B0 B1 B2]
    const uint32_t sA = smem_u32(smem);
    const uint32_t sB = sA + STAGES * A_STAGE_BYTES;
    float* Bbase = reinterpret_cast<float*>(smem + STAGES * A_STAGE_BYTES);

    const float* Xe = e_vw + (size_t)b * 65536 + n0;   // [128 K][512 N] slab
    const float* Xh = h_w  + (size_t)b * 65536 + n0;

    auto cp_chunk = [&](int i) {                 // chunk i -> stage i % 3
        const int s  = i % STAGES;
        const int k0 = i << 5;
        // A: g_W fp16 [128 m][32 k] -> pitch-40 rows; 512 x 16B, 2/thread
        const uint32_t ast = sA + (uint32_t)s * A_STAGE_BYTES;
        #pragma unroll
        for (int t = 0; t < 2; t++) {
            const int idx = tid + (t << 8);
            const int m = idx >> 2, c = idx & 3;
            cp16(ast + (uint32_t)(m * 80 + c * 16),
                 g_W + m * 256 + k0 + c * 8);
        }
        // B: X fp32 [32 k][64 n] -> pitch-68 rows; 512 x 16B, 2/thread
        const float* X = (k0 < 128) ? (Xe + (size_t)k0 * 512)
                                    : (Xh + (size_t)(k0 - 128) * 512);
        const uint32_t bst = sB + (uint32_t)s * B_STAGE_BYTES;
        #pragma unroll
        for (int t = 0; t < 2; t++) {
            const int idx = tid + (t << 8);
            const int k = idx >> 4, n4 = (idx & 15) << 2;
            cp16(bst + (uint32_t)(k * B_PITCH_F + n4) * 4,
                 X + (size_t)k * 512 + n4);
        }
    };

    const int wm = (wid >> 1) << 5;     // 0,32,64,96
    const int wn = (wid & 1) << 5;      // 0,32
    float acc[2][4][4];
    #pragma unroll
    for (int i = 0; i < 2; i++)
        #pragma unroll
        for (int j = 0; j < 4; j++)
            #pragma unroll
            for (int r = 0; r < 4; r++) acc[i][j][r] = 0.f;

    const int j8  = lane & 7;
    const int sel = lane >> 3;
    const int bn  = wn + (lane >> 2);        // B frag n column
    const int bk2 = (lane & 3) << 1;         // B frag k base within kstep

    auto compute = [&](int stage) {
        const uint32_t A = sA + (uint32_t)stage * A_STAGE_BYTES;
        const float* Bs = Bbase + stage * (B_STAGE_BYTES / 4);
        #pragma unroll
        for (int ks = 0; ks < 2; ks++) {
            const int kk = ks << 4;
            uint32_t afr[2][4];
            #pragma unroll
            for (int i = 0; i < 2; i++) {
                // x4 tiles: [m0 k0][m8 k0][m0 k8][m8 k8]
                const int row = wm + (i << 4) + ((sel & 1) << 3) + j8;
                const int kh  = kk + ((sel >> 1) << 3);
                ldmx4(afr[i], A + (uint32_t)(row * 80 + kh * 2));
            }
            // B frags from fp32 smem (canonical m16n8k16 B layout)
            uint32_t bq[4][2];
            #pragma unroll
            for (int t = 0; t < 4; t++) {
                const float* p = Bs + (kk + bk2) * B_PITCH_F + bn + (t << 3);
                const float f0 = p[0];
                const float f1 = p[B_PITCH_F];
                const float f2 = p[8 * B_PITCH_F];
                const float f3 = p[9 * B_PITCH_F];
                bq[t][0] = packh2(f0, f1);
                bq[t][1] = packh2(f2, f3);
            }
            #pragma unroll
            for (int i = 0; i < 2; i++)
                #pragma unroll
                for (int t = 0; t < 4; t++)
                    mma16816(acc[i][t], afr[i], bq[t][0], bq[t][1]);
        }
    };

    // -------- prologue: chunks 0,1 in flight --------
    cp_chunk(0); cp_commit();
    cp_chunk(1); cp_commit();

    // -------- mainloop: 8 K-chunks, one barrier per chunk --------
    for (int i = 0; i < 8; i++) {
        if (i < 7) cp_wait<1>(); else cp_wait<0>();
        __syncthreads();          // chunk-i data visible; compute(i-1) done
                                  // -> stage (i+2)%3 reusable
        if (i + 2 < 8) { cp_chunk(i + 2); cp_commit(); }
        compute(i % STAGES);
    }

    // -------- epilogue: direct STG (32B-sector complete per lane quad) -----
    const int r0 = lane >> 2;
    const int c0 = (lane & 3) << 1;
    float* outp = out + (size_t)b * 65536 + n0;
    #pragma unroll
    for (int i = 0; i < 2; i++) {
        const int r  = wm + (i << 4) + r0;
        const float bias0 = sbias[r];
        const float bias1 = sbias[r + 8];
        #pragma unroll
        for (int j = 0; j < 4; j++) {
            const int c = wn + (j << 3) + c0;
            float2 v0 = make_float2(acc[i][j][0] + bias0, acc[i][j][1] + bias0);
            float2 v1 = make_float2(acc[i][j][2] + bias1, acc[i][j][3] + bias1);
            *reinterpret_cast<float2*>(outp + (size_t)r * 512 + c)       = v0;
            *reinterpret_cast<float2*>(outp + (size_t)(r + 8) * 512 + c) = v1;
        }
    }
}

extern "C" void kernel_launch(void* const* d_in, const int* in_sizes, int n_in,
                              void* d_out, int out_size) {
    // metadata order: h_v(unused), h_w, e_vw, W_e, b_e, W_h, b_h
    const float* h_w  = (const float*)d_in[1];
    const float* e_vw = (const float*)d_in[2];
    const float* W_e  = (const float*)d_in[3];
    const float* b_e  = (const float*)d_in[4];
    const float* W_h  = (const float*)d_in[5];
    const float* b_h  = (const float*)d_in[6];
    float* out = (float*)d_out;

    prep_kernel<<<128, 256>>>(W_e, W_h, b_e, b_h);

    cudaFuncSetAttribute(msg_kernel, cudaFuncAttributeMaxDynamicSharedMemorySize,
                         SMEM_TOTAL);
    dim3 grid(8, 1024);
    msg_kernel<<<grid, 256, SMEM_TOTAL>>>(h_w, e_vw, out);
}

// round 9
// speedup vs baseline: 1.4487x; 1.0111x over previous
#include <cuda_runtime.h>
#include <cuda_fp16.h>
#include <cstdint>
#include <cstddef>

// ---------------------------------------------------------------------------
// Out[b] = [W_e | W_h](128x256) @ [e_vw[b]; h_w[b]](256x512) + (b_e + b_h)
// B=1024, M=128, K=256, N=512.
// Prep kernel: W -> fp16 global (k-contig) + fused bias.
// Main kernel: persistent CTA over NB=4 batches. Whole W held in smem
// (8 blocks x [128m x 32k] fp16, pitch 40 -> conflict-free ldmatrix),
// loaded ONCE per CTA -> kills the 512MB redundant A L2 stream of R8.
// B: cp.async fp32 3-stage ring, 2 chunks ahead. 8 warps x (32x32) tiles.
// ---------------------------------------------------------------------------

#define A_BLK_BYTES   (128 * 40 * 2)          // 10240 per 32-k chunk block
#define A_TOTAL_BYTES (8 * A_BLK_BYTES)       // 81920
#define B_PITCH_F     68                      // floats per B row
#define B_STAGE_BYTES (32 * B_PITCH_F * 4)    // 8704
#define B_STAGES      3
#define SMEM_TOTAL    (A_TOTAL_BYTES + B_STAGES * B_STAGE_BYTES)  // 108032
#define NB            4                       // batches per CTA
#define NCHUNK        (NB * 8)                // 32 K-chunks total

__device__ __half g_W[128 * 256];     // [m][k] fp16, k-contiguous
__device__ float  g_bias[128];

__global__ __launch_bounds__(256)
void prep_kernel(const float* __restrict__ W_e, const float* __restrict__ W_h,
                 const float* __restrict__ b_e, const float* __restrict__ b_h) {
    const int idx = blockIdx.x * 256 + threadIdx.x;     // 0..32767
    const int m = idx >> 8, k = idx & 255;
    const float v = (k < 128) ? W_e[m * 128 + k] : W_h[m * 128 + (k - 128)];
    g_W[idx] = __float2half(v);
    if (idx < 128) g_bias[idx] = b_e[idx] + b_h[idx];
}

static __device__ __forceinline__ uint32_t smem_u32(const void* p) {
    uint32_t a;
    asm("{ .reg .u64 t; cvta.to.shared.u64 t, %1; cvt.u32.u64 %0, t; }"
        : "=r"(a) : "l"(p));
    return a;
}
static __device__ __forceinline__ void ldmx4(uint32_t* r, uint32_t addr) {
    asm volatile("ldmatrix.sync.aligned.m8n8.x4.shared.b16 {%0,%1,%2,%3}, [%4];"
                 : "=r"(r[0]), "=r"(r[1]), "=r"(r[2]), "=r"(r[3]) : "r"(addr));
}
static __device__ __forceinline__ void mma16816(float* d, const uint32_t* a,
                                                uint32_t b0, uint32_t b1) {
    asm volatile(
        "mma.sync.aligned.m16n8k16.row.col.f32.f16.f16.f32 "
        "{%0,%1,%2,%3}, {%4,%5,%6,%7}, {%8,%9}, {%0,%1,%2,%3};"
        : "+f"(d[0]), "+f"(d[1]), "+f"(d[2]), "+f"(d[3])
        : "r"(a[0]), "r"(a[1]), "r"(a[2]), "r"(a[3]), "r"(b0), "r"(b1));
}
static __device__ __forceinline__ uint32_t packh2(float x, float y) {
    __half2 h = __floats2half2_rn(x, y);
    return *reinterpret_cast<uint32_t*>(&h);
}
static __device__ __forceinline__ void cp16(uint32_t smem_addr, const void* g) {
    asm volatile("cp.async.cg.shared.global [%0], [%1], 16;"
                 :: "r"(smem_addr), "l"(g) : "memory");
}
static __device__ __forceinline__ void cp_commit() {
    asm volatile("cp.async.commit_group;" ::: "memory");
}
template <int N>
static __device__ __forceinline__ void cp_wait() {
    asm volatile("cp.async.wait_group %0;" :: "n"(N) : "memory");
}

__global__ __launch_bounds__(256, 2)
void msg_kernel(const float* __restrict__ h_w, const float* __restrict__ e_vw,
                float* __restrict__ out) {
    extern __shared__ char smem[];
    __shared__ float sbias[128];

    const int tid  = threadIdx.x;
    const int lane = tid & 31;
    const int wid  = tid >> 5;
    const int b0   = blockIdx.y * NB;          // first batch of this CTA
    const int n0   = blockIdx.x << 6;          // 0..448 step 64

    if (tid < 128) sbias[tid] = g_bias[tid];

    const uint32_t sA = smem_u32(smem);
    const uint32_t sB = sA + A_TOTAL_BYTES;
    float* Bbase = reinterpret_cast<float*>(smem + A_TOTAL_BYTES);

    // -------- A prologue: whole prepacked W -> smem (one group) --------
    // 8 blocks x [128m x 32k] fp16, pitch 40 halves (80B rows).
    #pragma unroll
    for (int t = 0; t < 16; t++) {
        const int idx = tid + (t << 8);        // 0..4095 16B transfers
        const int c = idx >> 9;                // k-chunk block 0..7
        const int r = idx & 511;
        const int m = r >> 2, q = r & 3;
        cp16(sA + (uint32_t)(c * A_BLK_BYTES + m * 80 + q * 16),
             g_W + m * 256 + c * 32 + q * 8);
    }
    cp_commit();

    auto cp_B = [&](int ci) {                  // global chunk ci -> stage ci%3
        const int bat = b0 + (ci >> 3);
        const int k0  = (ci & 7) << 5;
        const float* X = (k0 < 128)
            ? (e_vw + (size_t)bat * 65536 + n0 + (size_t)k0 * 512)
            : (h_w  + (size_t)bat * 65536 + n0 + (size_t)(k0 - 128) * 512);
        const uint32_t bst = sB + (uint32_t)(ci % B_STAGES) * B_STAGE_BYTES;
        #pragma unroll
        for (int t = 0; t < 2; t++) {
            const int idx = tid + (t << 8);
            const int k = idx >> 4, n4 = (idx & 15) << 2;   // 32 rows x 64 n
            cp16(bst + (uint32_t)(k * B_PITCH_F + n4) * 4,
                 X + (size_t)k * 512 + n4);
        }
    };

    cp_B(0); cp_commit();
    cp_B(1); cp_commit();

    const int wm = (wid >> 1) << 5;     // 0,32,64,96
    const int wn = (wid & 1) << 5;      // 0,32
    float acc[2][4][4];
    #pragma unroll
    for (int i = 0; i < 2; i++)
        #pragma unroll
        for (int j = 0; j < 4; j++)
            #pragma unroll
            for (int r = 0; r < 4; r++) acc[i][j][r] = 0.f;

    const int j8  = lane & 7;
    const int sel = lane >> 3;
    const int bn  = wn + (lane >> 2);        // B frag n column
    const int bk2 = (lane & 3) << 1;         // B frag k base within kstep
    const int r0 = lane >> 2;
    const int c0 = (lane & 3) << 1;

    // -------- mainloop: NB*8 chunks, one barrier per chunk --------
    for (int ci = 0; ci < NCHUNK; ci++) {
        if (ci < NCHUNK - 1) cp_wait<1>(); else cp_wait<0>();
        __syncthreads();          // chunk-ci B visible; compute(ci-1) done
                                  // -> stage (ci+2)%3 reusable
        if (ci + 2 < NCHUNK) { cp_B(ci + 2); cp_commit(); }

        // compute: A block = k-chunk (ci&7), B stage = ci%3
        const uint32_t A = sA + (uint32_t)((ci & 7) * A_BLK_BYTES);
        const float* Bs = Bbase + (ci % B_STAGES) * (B_STAGE_BYTES / 4);
        #pragma unroll
        for (int ks = 0; ks < 2; ks++) {
            const int kk = ks << 4;
            uint32_t afr[2][4];
            #pragma unroll
            for (int i = 0; i < 2; i++) {
                const int row = wm + (i << 4) + ((sel & 1) << 3) + j8;
                const int kh  = kk + ((sel >> 1) << 3);
                ldmx4(afr[i], A + (uint32_t)(row * 80 + kh * 2));
            }
            uint32_t bq[4][2];
            #pragma unroll
            for (int t = 0; t < 4; t++) {
                const float* p = Bs + (kk + bk2) * B_PITCH_F + bn + (t << 3);
                const float f0 = p[0];
                const float f1 = p[B_PITCH_F];
                const float f2 = p[8 * B_PITCH_F];
                const float f3 = p[9 * B_PITCH_F];
                bq[t][0] = packh2(f0, f1);
                bq[t][1] = packh2(f2, f3);
            }
            #pragma unroll
            for (int i = 0; i < 2; i++)
                #pragma unroll
                for (int t = 0; t < 4; t++)
                    mma16816(acc[i][t], afr[i], bq[t][0], bq[t][1]);
        }

        // -------- per-batch epilogue (regs only, no smem) --------
        if ((ci & 7) == 7) {
            const int bat = b0 + (ci >> 3);
            float* outp = out + (size_t)bat * 65536 + n0;
            #pragma unroll
            for (int i = 0; i < 2; i++) {
                const int r  = wm + (i << 4) + r0;
                const float bias0 = sbias[r];
                const float bias1 = sbias[r + 8];
                #pragma unroll
                for (int j = 0; j < 4; j++) {
                    const int c = wn + (j << 3) + c0;
                    float2 v0 = make_float2(acc[i][j][0] + bias0,
                                            acc[i][j][1] + bias0);
                    float2 v1 = make_float2(acc[i][j][2] + bias1,
                                            acc[i][j][3] + bias1);
                    *reinterpret_cast<float2*>(outp + (size_t)r * 512 + c) = v0;
                    *reinterpret_cast<float2*>(outp + (size_t)(r + 8) * 512 + c) = v1;
                    acc[i][j][0] = 0.f; acc[i][j][1] = 0.f;
                    acc[i][j][2] = 0.f; acc[i][j][3] = 0.f;
                }
            }
        }
    }
}

extern "C" void kernel_launch(void* const* d_in, const int* in_sizes, int n_in,
                              void* d_out, int out_size) {
    // metadata order: h_v(unused), h_w, e_vw, W_e, b_e, W_h, b_h
    const float* h_w  = (const float*)d_in[1];
    const float* e_vw = (const float*)d_in[2];
    const float* W_e  = (const float*)d_in[3];
    const float* b_e  = (const float*)d_in[4];
    const float* W_h  = (const float*)d_in[5];
    const float* b_h  = (const float*)d_in[6];
    float* out = (float*)d_out;

    prep_kernel<<<128, 256>>>(W_e, W_h, b_e, b_h);

    cudaFuncSetAttribute(msg_kernel, cudaFuncAttributeMaxDynamicSharedMemorySize,
                         SMEM_TOTAL);
    dim3 grid(8, 256);
    msg_kernel<<<grid, 256, SMEM_TOTAL>>>(h_w, e_vw, out);
}

// round 10
// speedup vs baseline: 1.5069x; 1.0401x over previous
#include <cuda_runtime.h>
#include <cuda_fp16.h>
#include <cstdint>
#include <cstddef>

// ---------------------------------------------------------------------------
// Out[b] = [W_e | W_h](128x256) @ [e_vw[b]; h_w[b]](256x512) + (b_e + b_h)
// B=1024, M=128, K=256, N=512.
// Prep kernel: W -> fp16 global (k-contig) + fused bias.
// Main kernel: persistent CTA over NB=4 batches. Whole W in smem as one
// [128][264] fp16 buffer (528B rows, conflict-free ldmatrix), loaded once.
// B: cp.async fp32 FIVE-stage ring, FOUR chunks in flight (Little's law:
// ~16KB/SM needed to sustain DRAM; we hold 64KB/SM). One barrier per chunk.
// ---------------------------------------------------------------------------

#define A_PITCH_H     264                     // halves per W row (528 B)
#define A_TOTAL_BYTES (128 * A_PITCH_H * 2)   // 67584
#define B_PITCH_F     68                      // floats per B row
#define B_STAGE_BYTES (32 * B_PITCH_F * 4)    // 8704
#define B_STAGES      5
#define SMEM_TOTAL    (A_TOTAL_BYTES + B_STAGES * B_STAGE_BYTES)  // 111104
#define NB            4                       // batches per CTA
#define NCHUNK        (NB * 8)                // 32 K-chunks total

__device__ __half g_W[128 * 256];     // [m][k] fp16, k-contiguous
__device__ float  g_bias[128];

__global__ __launch_bounds__(256)
void prep_kernel(const float* __restrict__ W_e, const float* __restrict__ W_h,
                 const float* __restrict__ b_e, const float* __restrict__ b_h) {
    const int idx = blockIdx.x * 256 + threadIdx.x;     // 0..32767
    const int m = idx >> 8, k = idx & 255;
    const float v = (k < 128) ? W_e[m * 128 + k] : W_h[m * 128 + (k - 128)];
    g_W[idx] = __float2half(v);
    if (idx < 128) g_bias[idx] = b_e[idx] + b_h[idx];
}

static __device__ __forceinline__ uint32_t smem_u32(const void* p) {
    uint32_t a;
    asm("{ .reg .u64 t; cvta.to.shared.u64 t, %1; cvt.u32.u64 %0, t; }"
        : "=r"(a) : "l"(p));
    return a;
}
static __device__ __forceinline__ void ldmx4(uint32_t* r, uint32_t addr) {
    asm volatile("ldmatrix.sync.aligned.m8n8.x4.shared.b16 {%0,%1,%2,%3}, [%4];"
                 : "=r"(r[0]), "=r"(r[1]), "=r"(r[2]), "=r"(r[3]) : "r"(addr));
}
static __device__ __forceinline__ void mma16816(float* d, const uint32_t* a,
                                                uint32_t b0, uint32_t b1) {
    asm volatile(
        "mma.sync.aligned.m16n8k16.row.col.f32.f16.f16.f32 "
        "{%0,%1,%2,%3}, {%4,%5,%6,%7}, {%8,%9}, {%0,%1,%2,%3};"
        : "+f"(d[0]), "+f"(d[1]), "+f"(d[2]), "+f"(d[3])
        : "r"(a[0]), "r"(a[1]), "r"(a[2]), "r"(a[3]), "r"(b0), "r"(b1));
}
static __device__ __forceinline__ uint32_t packh2(float x, float y) {
    __half2 h = __floats2half2_rn(x, y);
    return *reinterpret_cast<uint32_t*>(&h);
}
static __device__ __forceinline__ void cp16(uint32_t smem_addr, const void* g) {
    asm volatile("cp.async.cg.shared.global [%0], [%1], 16;"
                 :: "r"(smem_addr), "l"(g) : "memory");
}
static __device__ __forceinline__ void cp_commit() {
    asm volatile("cp.async.commit_group;" ::: "memory");
}
template <int N>
static __device__ __forceinline__ void cp_wait() {
    asm volatile("cp.async.wait_group %0;" :: "n"(N) : "memory");
}

__global__ __launch_bounds__(256, 2)
void msg_kernel(const float* __restrict__ h_w, const float* __restrict__ e_vw,
                float* __restrict__ out) {
    extern __shared__ char smem[];
    __shared__ float sbias[128];

    const int tid  = threadIdx.x;
    const int lane = tid & 31;
    const int wid  = tid >> 5;
    const int b0   = blockIdx.y * NB;          // first batch of this CTA
    const int n0   = blockIdx.x << 6;          // 0..448 step 64

    if (tid < 128) sbias[tid] = g_bias[tid];

    const uint32_t sA = smem_u32(smem);
    const uint32_t sB = sA + A_TOTAL_BYTES;
    float* Bbase = reinterpret_cast<float*>(smem + A_TOTAL_BYTES);

    // -------- A prologue: whole prepacked W -> smem (one group) --------
    // [128 m][256 k] fp16, pitch 264 halves (528B rows).
    #pragma unroll
    for (int t = 0; t < 16; t++) {
        const int idx = tid + (t << 8);        // 0..4095 16B transfers
        const int m = idx >> 5, q = idx & 31;
        cp16(sA + (uint32_t)(m * 528 + q * 16), g_W + m * 256 + q * 8);
    }
    cp_commit();                               // group: A

    auto cp_B = [&](int ci) {                  // global chunk ci -> stage ci%5
        const int bat = b0 + (ci >> 3);
        const int k0  = (ci & 7) << 5;
        const float* X = (k0 < 128)
            ? (e_vw + (size_t)bat * 65536 + n0 + (size_t)k0 * 512)
            : (h_w  + (size_t)bat * 65536 + n0 + (size_t)(k0 - 128) * 512);
        const uint32_t bst = sB + (uint32_t)(ci % B_STAGES) * B_STAGE_BYTES;
        #pragma unroll
        for (int t = 0; t < 2; t++) {
            const int idx = tid + (t << 8);
            const int k = idx >> 4, n4 = (idx & 15) << 2;   // 32 rows x 64 n
            cp16(bst + (uint32_t)(k * B_PITCH_F + n4) * 4,
                 X + (size_t)k * 512 + n4);
        }
        cp_commit();
    };

    cp_B(0); cp_B(1); cp_B(2); cp_B(3);        // 4 chunks in flight

    const int wm = (wid >> 1) << 5;     // 0,32,64,96
    const int wn = (wid & 1) << 5;      // 0,32
    float acc[2][4][4];
    #pragma unroll
    for (int i = 0; i < 2; i++)
        #pragma unroll
        for (int j = 0; j < 4; j++)
            #pragma unroll
            for (int r = 0; r < 4; r++) acc[i][j][r] = 0.f;

    const int j8  = lane & 7;
    const int sel = lane >> 3;
    const int bn  = wn + (lane >> 2);        // B frag n column
    const int bk2 = (lane & 3) << 1;         // B frag k base within kstep
    const int r0  = lane >> 2;
    const int c0  = (lane & 3) << 1;

    // ldmatrix row bases (constant): row = wm + 16i + 8*(sel&1) + j8
    uint32_t aRow[2];
    #pragma unroll
    for (int i = 0; i < 2; i++)
        aRow[i] = sA + (uint32_t)((wm + (i << 4) + ((sel & 1) << 3) + j8) * 528
                                  + ((sel >> 1) << 3) * 2);

    // -------- mainloop: NB*8 chunks, one barrier per chunk --------
    // Wait accounting: before iter ci, committed groups = 1(A) +
    // min(NCHUNK, ci+4). Chunks 0..ci complete <=> outstanding <= N where
    // N = 3 steady-state, then 2/1/0 on the last three iterations.
    for (int ci = 0; ci < NCHUNK; ci++) {
        if      (ci < NCHUNK - 3) cp_wait<3>();
        else if (ci == NCHUNK - 3) cp_wait<2>();
        else if (ci == NCHUNK - 2) cp_wait<1>();
        else                       cp_wait<0>();
        __syncthreads();          // chunk-ci B visible; compute(ci-1) done
                                  // -> stage (ci+4)%5 == (ci-1)%5 reusable
        if (ci + 4 < NCHUNK) cp_B(ci + 4);

        // compute: A columns k0 = (ci&7)*32, B stage = ci%5
        const uint32_t kBase = (uint32_t)(((ci & 7) << 5) * 2);   // bytes
        const float* Bs = Bbase + (ci % B_STAGES) * (B_STAGE_BYTES / 4);
        #pragma unroll
        for (int ks = 0; ks < 2; ks++) {
            const int kk = ks << 4;
            uint32_t afr[2][4];
            #pragma unroll
            for (int i = 0; i < 2; i++)
                ldmx4(afr[i], aRow[i] + kBase + (uint32_t)(kk * 2));
            uint32_t bq[4][2];
            #pragma unroll
            for (int t = 0; t < 4; t++) {
                const float* p = Bs + (kk + bk2) * B_PITCH_F + bn + (t << 3);
                const float f0 = p[0];
                const float f1 = p[B_PITCH_F];
                const float f2 = p[8 * B_PITCH_F];
                const float f3 = p[9 * B_PITCH_F];
                bq[t][0] = packh2(f0, f1);
                bq[t][1] = packh2(f2, f3);
            }
            #pragma unroll
            for (int i = 0; i < 2; i++)
                #pragma unroll
                for (int t = 0; t < 4; t++)
                    mma16816(acc[i][t], afr[i], bq[t][0], bq[t][1]);
        }

        // -------- per-batch epilogue (regs only, no smem) --------
        if ((ci & 7) == 7) {
            const int bat = b0 + (ci >> 3);
            float* outp = out + (size_t)bat * 65536 + n0;
            #pragma unroll
            for (int i = 0; i < 2; i++) {
                const int r  = wm + (i << 4) + r0;
                const float bias0 = sbias[r];
                const float bias1 = sbias[r + 8];
                #pragma unroll
                for (int j = 0; j < 4; j++) {
                    const int c = wn + (j << 3) + c0;
                    float2 v0 = make_float2(acc[i][j][0] + bias0,
                                            acc[i][j][1] + bias0);
                    float2 v1 = make_float2(acc[i][j][2] + bias1,
                                            acc[i][j][3] + bias1);
                    *reinterpret_cast<float2*>(outp + (size_t)r * 512 + c) = v0;
                    *reinterpret_cast<float2*>(outp + (size_t)(r + 8) * 512 + c) = v1;
                    acc[i][j][0] = 0.f; acc[i][j][1] = 0.f;
                    acc[i][j][2] = 0.f; acc[i][j][3] = 0.f;
                }
            }
        }
    }
}

extern "C" void kernel_launch(void* const* d_in, const int* in_sizes, int n_in,
                              void* d_out, int out_size) {
    // metadata order: h_v(unused), h_w, e_vw, W_e, b_e, W_h, b_h
    const float* h_w  = (const float*)d_in[1];
    const float* e_vw = (const float*)d_in[2];
    const float* W_e  = (const float*)d_in[3];
    const float* b_e  = (const float*)d_in[4];
    const float* W_h  = (const float*)d_in[5];
    const float* b_h  = (const float*)d_in[6];
    float* out = (float*)d_out;

    prep_kernel<<<128, 256>>>(W_e, W_h, b_e, b_h);

    cudaFuncSetAttribute(msg_kernel, cudaFuncAttributeMaxDynamicSharedMemorySize,
                         SMEM_TOTAL);
    dim3 grid(8, 256);
    msg_kernel<<<grid, 256, SMEM_TOTAL>>>(h_w, e_vw, out);
}